// round 5
// baseline (speedup 1.0000x reference)
#include <cuda_runtime.h>
#include <stdint.h>

#define BB   16
#define CH   3
#define HH   1024
#define WW   1024
#define NCRACK 8
#define PIX    (HH * WW)
#define CRACK_VAL 0.05f

#define NBLOCKS (148 * 8)        // one full wave on GB300 (152 SMs; 148 keeps it ≤1 wave)
#define NPAIRS  (HH * BB)        // 16384 (row, batch) pairs

// ---------------------------------------------------------------------------
// Persistent single-wave fused kernel. Each block grid-strides over
// (row, batch) pairs; per pair it builds the 1024-bit row crack mask in smem
// (closed-form Bresenham inversion, validated rel_err=0 in R2-R4), then
// streams all 3 channels of that row with __ldcs/__stcs.
// rowmask is double-buffered so each loop iteration needs only 2 barriers.
// ---------------------------------------------------------------------------
__global__ __launch_bounds__(256) void fused_crack_kernel(
    const float4* __restrict__ x, float4* __restrict__ out,
    const int* __restrict__ ep)
{
    __shared__ int2     iv[NCRACK];
    __shared__ unsigned rowmask[2][32];

    unsigned buf = 0;
    for (unsigned p = blockIdx.x; p < NPAIRS; p += NBLOCKS, buf ^= 1u) {
        const unsigned row = p & (HH - 1u);
        const unsigned b   = p >> 10;

        if (threadIdx.x < NCRACK) {
            const int* e = ep + (b * NCRACK + threadIdx.x) * 4;  // (y0,x0,y1,x1)
            int y0 = e[0], x0 = e[1], y1 = e[2], x1 = e[3];
            int dx = abs(x1 - x0);
            int dy = abs(y1 - y0);
            int sx = (x0 < x1) ? 1 : -1;
            int sy = (y0 < y1) ? 1 : -1;
            int y  = (int)row;

            int xlo = 1, xhi = 0;            // empty
            if (dx >= dy) {
                int m = sy * (y - y0);
                if (m >= 0 && m <= dy) {
                    int tlo, thi;
                    if (dy == 0)      { tlo = 0; thi = dx; }
                    else if (m == 0)  { tlo = 0; thi = dx / (2 * dy); }
                    else {
                        tlo = (dx * (2 * m - 1)) / (2 * dy) + 1;
                        thi = (dx * (2 * m + 1)) / (2 * dy);
                    }
                    thi = min(thi, dx);
                    int xa = x0 + sx * tlo;
                    int xb = x0 + sx * thi;
                    xlo = min(xa, xb);
                    xhi = max(xa, xb);
                }
            } else {
                int t = sy * (y - y0);
                if (t >= 0 && t <= dy) {
                    int a  = 2 * t * dx - dy;
                    int b2 = 2 * dy;
                    int k  = max(0, (a + b2 - 1) / b2);
                    xlo = xhi = x0 + sx * k;
                }
            }
            iv[threadIdx.x] = make_int2(xlo, xhi);
        }
        __syncthreads();                     // iv ready; prev-iter rowmask[buf] readers done

        if (threadIdx.x < 32) {
            int base = (int)(threadIdx.x * 32u);
            unsigned w = 0;
            #pragma unroll
            for (int i = 0; i < NCRACK; i++) {
                int lo = max(iv[i].x - base, 0);
                int hi = min(iv[i].y - base, 31);
                if (lo <= hi) {
                    int len = hi - lo + 1;
                    w |= (0xFFFFFFFFu >> (32 - len)) << lo;
                }
            }
            rowmask[buf][threadIdx.x] = w;
        }
        __syncthreads();                     // rowmask[buf] ready

        const unsigned m =
            (rowmask[buf][threadIdx.x >> 3] >> ((threadIdx.x & 7u) * 4u)) & 0xFu;

        const unsigned p4   = row * 256u + threadIdx.x;
        const unsigned base = b * CH * (PIX / 4) + p4;

        float4 v0 = __ldcs(&x[base]);
        float4 v1 = __ldcs(&x[base +     (PIX / 4)]);
        float4 v2 = __ldcs(&x[base + 2 * (PIX / 4)]);

        #define APPLY(v) do { \
            (v).x = (m & 1u) ? CRACK_VAL : fminf(fmaxf((v).x, 0.0f), 1.0f); \
            (v).y = (m & 2u) ? CRACK_VAL : fminf(fmaxf((v).y, 0.0f), 1.0f); \
            (v).z = (m & 4u) ? CRACK_VAL : fminf(fmaxf((v).z, 0.0f), 1.0f); \
            (v).w = (m & 8u) ? CRACK_VAL : fminf(fmaxf((v).w, 0.0f), 1.0f); \
        } while (0)

        APPLY(v0); APPLY(v1); APPLY(v2);

        __stcs(&out[base],                 v0);
        __stcs(&out[base +     (PIX / 4)], v1);
        __stcs(&out[base + 2 * (PIX / 4)], v2);
    }
}

// ---------------------------------------------------------------------------
extern "C" void kernel_launch(void* const* d_in, const int* in_sizes, int n_in,
                              void* d_out, int out_size) {
    const float* x   = (const float*)d_in[0];   // [16,3,1024,1024] f32
    const int*   ep  = (const int*)d_in[1];     // [16,8,4] i32
    float*       out = (float*)d_out;

    fused_crack_kernel<<<NBLOCKS, 256>>>((const float4*)x, (float4*)out, ep);
}

// round 7
// speedup vs baseline: 1.1364x; 1.1364x over previous
#include <cuda_runtime.h>
#include <stdint.h>

#define BB   16
#define CH   3
#define HH   1024
#define WW   1024
#define NCRACK 8
#define PIX    (HH * WW)
#define CRACK_VAL 0.05f

// ---------------------------------------------------------------------------
// One block per (row, batch), all 3 channels. R4 structure with:
//   - global loads issued BEFORE the mask prologue (latency hides prologue)
//   - prologue collapsed into warp 0 via shuffles (one barrier, no iv smem)
//
// Closed-form Bresenham inversion (validated rel_err=0 in R2-R5):
//   x-major (dx>=dy), m = sy*(y-y0) in [0,dy]:
//     m==0: t in [0, floor(dx/(2dy))] (dy==0: [0,dx])
//     m>=1: t in [floor(dx(2m-1)/(2dy))+1, floor(dx(2m+1)/(2dy))], t<=dx
//     x = x0 + sx*t (contiguous interval)
//   y-major: single pixel x = x0 + sx*max(0, ceil((2t*dx-dy)/(2dy)))
// ---------------------------------------------------------------------------
__global__ __launch_bounds__(256) void fused_crack_kernel(
    const float4* __restrict__ x, float4* __restrict__ out,
    const int* __restrict__ ep)
{
    __shared__ unsigned rowmask[32];     // 1024-bit mask for this row

    const unsigned row = blockIdx.x;     // y
    const unsigned b   = blockIdx.y;

    // ---- issue streaming loads first; prologue executes in their shadow ----
    const unsigned p4   = row * 256u + threadIdx.x;
    const unsigned base = b * CH * (PIX / 4) + p4;

    float4 v0 = x[base];
    float4 v1 = x[base +     (PIX / 4)];
    float4 v2 = x[base + 2 * (PIX / 4)];

    // ---- warp 0 builds the row mask (shuffle-based, single barrier) ----
    if (threadIdx.x < 32) {
        const unsigned lane = threadIdx.x;
        int xlo = 1, xhi = 0;            // empty interval

        if (lane < NCRACK) {
            const int4 e = *(const int4*)(ep + (b * NCRACK + lane) * 4); // (y0,x0,y1,x1)
            int y0 = e.x, x0 = e.y, y1 = e.z, x1 = e.w;
            int dx = abs(x1 - x0);
            int dy = abs(y1 - y0);
            int sx = (x0 < x1) ? 1 : -1;
            int sy = (y0 < y1) ? 1 : -1;
            int y  = (int)row;

            if (dx >= dy) {
                int m = sy * (y - y0);
                if (m >= 0 && m <= dy) {
                    int tlo, thi;
                    if (dy == 0)      { tlo = 0; thi = dx; }
                    else if (m == 0)  { tlo = 0; thi = dx / (2 * dy); }
                    else {
                        tlo = (dx * (2 * m - 1)) / (2 * dy) + 1;
                        thi = (dx * (2 * m + 1)) / (2 * dy);
                    }
                    thi = min(thi, dx);
                    int xa = x0 + sx * tlo;
                    int xb = x0 + sx * thi;
                    xlo = min(xa, xb);
                    xhi = max(xa, xb);
                }
            } else {
                int t = sy * (y - y0);
                if (t >= 0 && t <= dy) {
                    int a  = 2 * t * dx - dy;
                    int b2 = 2 * dy;
                    int k  = max(0, (a + b2 - 1) / b2);
                    xlo = xhi = x0 + sx * k;
                }
            }
        }

        // broadcast 8 intervals to all lanes; each lane builds its mask word
        const int wbase = (int)(lane * 32u);
        unsigned w = 0;
        #pragma unroll
        for (int i = 0; i < NCRACK; i++) {
            int lo = __shfl_sync(0xFFFFFFFFu, xlo, i);
            int hi = __shfl_sync(0xFFFFFFFFu, xhi, i);
            lo = max(lo - wbase, 0);
            hi = min(hi - wbase, 31);
            if (lo <= hi) {
                int len = hi - lo + 1;
                w |= (0xFFFFFFFFu >> (32 - len)) << lo;
            }
        }
        rowmask[lane] = w;
    }
    __syncthreads();

    const unsigned m = (rowmask[threadIdx.x >> 3] >> ((threadIdx.x & 7u) * 4u)) & 0xFu;

    #define APPLY(v) do { \
        (v).x = (m & 1u) ? CRACK_VAL : fminf(fmaxf((v).x, 0.0f), 1.0f); \
        (v).y = (m & 2u) ? CRACK_VAL : fminf(fmaxf((v).y, 0.0f), 1.0f); \
        (v).z = (m & 4u) ? CRACK_VAL : fminf(fmaxf((v).z, 0.0f), 1.0f); \
        (v).w = (m & 8u) ? CRACK_VAL : fminf(fmaxf((v).w, 0.0f), 1.0f); \
    } while (0)

    APPLY(v0); APPLY(v1); APPLY(v2);

    out[base]                 = v0;
    out[base +     (PIX / 4)] = v1;
    out[base + 2 * (PIX / 4)] = v2;
}

// ---------------------------------------------------------------------------
extern "C" void kernel_launch(void* const* d_in, const int* in_sizes, int n_in,
                              void* d_out, int out_size) {
    const float* x   = (const float*)d_in[0];   // [16,3,1024,1024] f32
    const int*   ep  = (const int*)d_in[1];     // [16,8,4] i32
    float*       out = (float*)d_out;

    dim3 grid(HH, BB);                           // one block per (row, batch)
    fused_crack_kernel<<<grid, 256>>>((const float4*)x, (float4*)out, ep);
}